// round 2
// baseline (speedup 1.0000x reference)
#include <cuda_runtime.h>
#include <cuda_bf16.h>
#include <cstdint>

// ============================================================================
// VQ quantizer: for each of N=131072 vectors z (C=256), find argmin_k over
// K=512 codes of ||z-e_k||^2, output e[argmin] in [B,C,H,W] layout.
//
// Pipeline:
//   1) prep_e:    e fp32 -> bf16 codebook + fp32 ||e_k||^2
//   2) zero:      reset rescore queue counter
//   3) gemm:      bf16 mma.sync GEMM (scores s_k = ||e_k||^2 - 2 z.e_k),
//                 fused running argmin + candidate collection (margin=1.5)
//   4) classify:  1 candidate -> done; else push to rescore queue
//   5) rescore:   fp64 exact scores for queued vectors' candidates
//   6) gather:    out[b,c,h,w] = e[best[n]][c], smem-transposed coalesced
// ============================================================================

#define BATCH 128
#define CDIM  256
#define HW    1024
#define NVEC  (BATCH * HW)        // 131072
#define KCODE 512
#define CAP   16
#define MARGIN 1.5f

#define BM 128            // vectors per gemm block
#define BN 64             // codes per chunk
#define NCHUNK (KCODE / BN)
#define ZSTRIDE 264       // bf16 elements per smem row (256 + 8 pad)

// --------------------------- scratch (device globals) -----------------------
__device__ __nv_bfloat16 g_eb[KCODE * CDIM];
__device__ float         g_enf[KCODE];
__device__ int           g_cnt[NVEC];
__device__ int           g_cand[NVEC * CAP];
__device__ int           g_best[NVEC];
__device__ int           g_queue[NVEC];
__device__ int           g_qcnt;

// --------------------------- helpers ----------------------------------------
__device__ __forceinline__ unsigned long long pack_key(float s, int k) {
    unsigned int u = __float_as_uint(s);
    u = (s < 0.0f) ? ~u : (u | 0x80000000u);
    return (((unsigned long long)u) << 32) | (unsigned int)k;
}
__device__ __forceinline__ float unpack_score(unsigned long long key) {
    unsigned int u = (unsigned int)(key >> 32);
    if (u & 0x80000000u) return __uint_as_float(u & 0x7FFFFFFFu);
    return __uint_as_float(~u);
}

__device__ __forceinline__ void mma16816(float* c, const uint32_t* a, const uint32_t* b) {
    asm volatile(
        "mma.sync.aligned.m16n8k16.row.col.f32.bf16.bf16.f32 "
        "{%0,%1,%2,%3}, {%4,%5,%6,%7}, {%8,%9}, {%0,%1,%2,%3};"
        : "+f"(c[0]), "+f"(c[1]), "+f"(c[2]), "+f"(c[3])
        : "r"(a[0]), "r"(a[1]), "r"(a[2]), "r"(a[3]), "r"(b[0]), "r"(b[1]));
}

// --------------------------- 1) codebook prep --------------------------------
__global__ void k_prep_e(const float* __restrict__ e) {
    int k = blockIdx.x;           // 512 blocks
    int c = threadIdx.x;          // 256 threads
    float v = e[k * CDIM + c];
    g_eb[k * CDIM + c] = __float2bfloat16(v);
    float ss = v * v;
    #pragma unroll
    for (int off = 16; off > 0; off >>= 1)
        ss += __shfl_xor_sync(0xFFFFFFFFu, ss, off);
    __shared__ float part[8];
    if ((c & 31) == 0) part[c >> 5] = ss;
    __syncthreads();
    if (c == 0) {
        float t = 0.0f;
        #pragma unroll
        for (int i = 0; i < 8; i++) t += part[i];
        g_enf[k] = t;
    }
}

// --------------------------- 2) queue reset ----------------------------------
__global__ void k_zero() { g_qcnt = 0; }

// --------------------------- 3) GEMM + argmin + candidates -------------------
__global__ void __launch_bounds__(256)
k_gemm_argmin(const float* __restrict__ x) {
    extern __shared__ char smraw[];
    __nv_bfloat16* zsh = (__nv_bfloat16*)smraw;                     // 128 x 264
    __nv_bfloat16* esh = zsh + BM * ZSTRIDE;                        // 64  x 264
    float* ensh = (float*)(esh + BN * ZSTRIDE);                     // 512
    unsigned long long* runmin = (unsigned long long*)(ensh + KCODE); // 128
    int* scnt  = (int*)(runmin + BM);                               // 128
    int* scand = scnt + BM;                                         // 128*CAP

    const int tid = threadIdx.x;
    const int n0  = blockIdx.x * BM;
    const int bb  = n0 >> 10;
    const int hw0 = n0 & 1023;

    if (tid < BM) { runmin[tid] = ~0ull; scnt[tid] = 0; }
    for (int i = tid; i < KCODE; i += 256) ensh[i] = g_enf[i];

    // load z tile [128 hw][256 c] from x[b, c, hw0..hw0+127], transposed+bf16
    const float* xb = x + (size_t)bb * CDIM * HW + hw0;
    for (int t = tid; t < CDIM * BM; t += 256) {
        int c = t >> 7, i = t & 127;
        zsh[i * ZSTRIDE + c] = __float2bfloat16(xb[(size_t)c * HW + i]);
    }
    __syncthreads();

    const int lane = tid & 31, wid = tid >> 5;
    const int wm = wid & 3, wn = wid >> 2;   // 4x2 warp grid
    const int qr = lane >> 2, qc = lane & 3;

    for (int ck = 0; ck < NCHUNK; ck++) {
        // load e chunk [64 codes][256 c] bf16 (uint4 = 8 bf16)
        for (int t = tid; t < BN * 32; t += 256) {
            int r = t >> 5, s = t & 31;
            *(uint4*)&esh[r * ZSTRIDE + s * 8] =
                *(const uint4*)&g_eb[(size_t)(ck * BN + r) * CDIM + s * 8];
        }
        __syncthreads();

        float acc[2][4][4];
        #pragma unroll
        for (int mt = 0; mt < 2; mt++)
            #pragma unroll
            for (int nt = 0; nt < 4; nt++)
                #pragma unroll
                for (int i = 0; i < 4; i++) acc[mt][nt][i] = 0.0f;

        #pragma unroll
        for (int kk = 0; kk < 16; kk++) {
            const int kb = kk * 16;
            uint32_t afr[2][4];
            #pragma unroll
            for (int mt = 0; mt < 2; mt++) {
                int r = wm * 32 + mt * 16 + qr;
                afr[mt][0] = *(const uint32_t*)&zsh[r * ZSTRIDE + kb + 2 * qc];
                afr[mt][1] = *(const uint32_t*)&zsh[(r + 8) * ZSTRIDE + kb + 2 * qc];
                afr[mt][2] = *(const uint32_t*)&zsh[r * ZSTRIDE + kb + 8 + 2 * qc];
                afr[mt][3] = *(const uint32_t*)&zsh[(r + 8) * ZSTRIDE + kb + 8 + 2 * qc];
            }
            uint32_t bfr[4][2];
            #pragma unroll
            for (int nt = 0; nt < 4; nt++) {
                int n = wn * 32 + nt * 8 + qr;
                bfr[nt][0] = *(const uint32_t*)&esh[n * ZSTRIDE + kb + 2 * qc];
                bfr[nt][1] = *(const uint32_t*)&esh[n * ZSTRIDE + kb + 8 + 2 * qc];
            }
            #pragma unroll
            for (int mt = 0; mt < 2; mt++)
                #pragma unroll
                for (int nt = 0; nt < 4; nt++)
                    mma16816(acc[mt][nt], afr[mt], bfr[nt]);
        }

        // ---- per-chunk argmin reduction into runmin ----
        #pragma unroll
        for (int mt = 0; mt < 2; mt++) {
            #pragma unroll
            for (int h = 0; h < 2; h++) {
                int row = wm * 32 + mt * 16 + h * 8 + qr;
                unsigned long long best = ~0ull;
                #pragma unroll
                for (int nt = 0; nt < 4; nt++) {
                    #pragma unroll
                    for (int j = 0; j < 2; j++) {
                        int kg = ck * BN + wn * 32 + nt * 8 + 2 * qc + j;
                        float s = ensh[kg] - 2.0f * acc[mt][nt][h * 2 + j];
                        unsigned long long key = pack_key(s, kg);
                        best = (key < best) ? key : best;
                    }
                }
                unsigned long long o;
                o = __shfl_xor_sync(0xFFFFFFFFu, best, 1); best = (o < best) ? o : best;
                o = __shfl_xor_sync(0xFFFFFFFFu, best, 2); best = (o < best) ? o : best;
                if (qc == 0) atomicMin(&runmin[row], best);
            }
        }
        __syncthreads();

        // ---- candidate collection vs updated running min ----
        #pragma unroll
        for (int mt = 0; mt < 2; mt++) {
            #pragma unroll
            for (int h = 0; h < 2; h++) {
                int row = wm * 32 + mt * 16 + h * 8 + qr;
                float thr = unpack_score(runmin[row]) + MARGIN;
                #pragma unroll
                for (int nt = 0; nt < 4; nt++) {
                    #pragma unroll
                    for (int j = 0; j < 2; j++) {
                        int kg = ck * BN + wn * 32 + nt * 8 + 2 * qc + j;
                        float s = ensh[kg] - 2.0f * acc[mt][nt][h * 2 + j];
                        if (s <= thr) {
                            int p = atomicAdd(&scnt[row], 1);
                            if (p < CAP) scand[row * CAP + p] = kg;
                        }
                    }
                }
            }
        }
        __syncthreads();
    }

    for (int t = tid; t < BM; t += 256) g_cnt[n0 + t] = scnt[t];
    for (int t = tid; t < BM * CAP; t += 256) g_cand[(size_t)n0 * CAP + t] = scand[t];
}

// --------------------------- 4) classify -------------------------------------
__global__ void k_classify() {
    int n = blockIdx.x * blockDim.x + threadIdx.x;
    if (n >= NVEC) return;
    int cnt = g_cnt[n];
    if (cnt == 1) {
        g_best[n] = g_cand[(size_t)n * CAP];
    } else {
        int p = atomicAdd(&g_qcnt, 1);
        g_queue[p] = n;
    }
}

// --------------------------- 5) fp64 exact rescore ---------------------------
__global__ void k_rescore(const float* __restrict__ x, const float* __restrict__ e) {
    const int lane = threadIdx.x & 31;
    const int wglob = (blockIdx.x * blockDim.x + threadIdx.x) >> 5;
    const int nwarps = (gridDim.x * blockDim.x) >> 5;
    const int q = g_qcnt;

    for (int it = wglob; it < q; it += nwarps) {
        int n = g_queue[it];
        int bb = n >> 10, hw = n & 1023;
        const float* xp = x + (size_t)bb * CDIM * HW + hw;
        float z[8];
        #pragma unroll
        for (int j = 0; j < 8; j++) z[j] = xp[(size_t)(lane + 32 * j) * HW];

        int cnt = g_cnt[n];
        double bestS = 1e300;
        int bestK = 0x7FFFFFFF;
        const bool overflow = (cnt > CAP);
        const int iters = overflow ? KCODE : cnt;
        for (int i = 0; i < iters; i++) {
            int k = overflow ? i : g_cand[(size_t)n * CAP + i];
            const float* er = e + (size_t)k * CDIM;
            double d = 0.0;
            #pragma unroll
            for (int j = 0; j < 8; j++)
                d += (double)z[j] * (double)er[lane + 32 * j];
            #pragma unroll
            for (int off = 16; off > 0; off >>= 1)
                d += __shfl_xor_sync(0xFFFFFFFFu, d, off);
            // exact fp64 squared distance (minus the constant ||z||^2 term)
            double en = 0.0;
            #pragma unroll
            for (int j = 0; j < 8; j++) {
                double ev = (double)er[lane + 32 * j];
                en += ev * ev;
            }
            #pragma unroll
            for (int off = 16; off > 0; off >>= 1)
                en += __shfl_xor_sync(0xFFFFFFFFu, en, off);
            double s = en - 2.0 * d;
            if (s < bestS || (s == bestS && k < bestK)) { bestS = s; bestK = k; }
        }
        if (lane == 0) g_best[n] = bestK;
    }
}

// --------------------------- 6) gather ---------------------------------------
__global__ void k_gather(const float* __restrict__ e, float* __restrict__ out) {
    __shared__ float rows[32][257];
    __shared__ int sidx[32];
    const int tid = threadIdx.x, lane = tid & 31, wid = tid >> 5;
    const int n0 = blockIdx.x * 32;
    const int bb = n0 >> 10, hw0 = n0 & 1023;

    if (tid < 32) sidx[tid] = g_best[n0 + tid];
    __syncthreads();

    for (int v = wid; v < 32; v += 8) {
        const float* er = e + (size_t)sidx[v] * CDIM;
        #pragma unroll
        for (int j = 0; j < 8; j++) rows[v][lane + 32 * j] = er[lane + 32 * j];
    }
    __syncthreads();

    for (int c = wid; c < CDIM; c += 8)
        out[((size_t)bb * CDIM + c) * HW + hw0 + lane] = rows[lane][c];
}

// --------------------------- launch ------------------------------------------
extern "C" void kernel_launch(void* const* d_in, const int* in_sizes, int n_in,
                              void* d_out, int out_size) {
    const float* x = (const float*)d_in[0];
    const float* e = (const float*)d_in[1];
    if (n_in >= 2 && in_sizes[0] == KCODE * CDIM) {  // robust to input order
        x = (const float*)d_in[1];
        e = (const float*)d_in[0];
    }
    float* out = (float*)d_out;

    const int smem_b = (BM + BN) * ZSTRIDE * 2    // z + e tiles (bf16)
                     + KCODE * 4                  // ensh
                     + BM * 8                     // runmin
                     + BM * 4                     // scnt
                     + BM * CAP * 4;              // scand
    cudaFuncSetAttribute(k_gemm_argmin, cudaFuncAttributeMaxDynamicSharedMemorySize, smem_b);

    k_prep_e<<<KCODE, CDIM>>>(e);
    k_zero<<<1, 1>>>();
    k_gemm_argmin<<<NVEC / BM, 256, smem_b>>>(x);
    k_classify<<<NVEC / 256, 256>>>();
    k_rescore<<<296, 256>>>(x, e);
    k_gather<<<NVEC / 32, 256>>>(e, out);
}

// round 4
// speedup vs baseline: 1.1322x; 1.1322x over previous
#include <cuda_runtime.h>
#include <cuda_bf16.h>
#include <cstdint>

// ============================================================================
// VQ quantizer: for each of N=131072 vectors z (C=256), argmin_k over K=512
// codes of ||z-e_k||^2, output e[argmin] in [B,C,H,W] layout.
//
//   1) prep_e:  e fp32 -> bf16 codebook + fp32 ||e_k||^2
//   2) zero:    reset rescore queue counter
//   3) gemm:    bf16 mma.sync GEMM (s_k = ||e_k||^2 - 2 z.e_k), warp-owns-rows
//               running-min + margin candidate collection + inline classify
//   4) rescore: fp64 exact scores for ambiguous rows' candidates
//   5) gather:  out[b,c,h,w] = e[best[n]][c]
// ============================================================================

#define BATCH 128
#define CDIM  256
#define HW    1024
#define NVEC  (BATCH * HW)
#define KCODE 512
#define CAP   16
#define MARGIN 2.0f

#define BM 128
#define BN 64
#define NCHUNK (KCODE / BN)
#define ZS  264                 // bf16 elements per smem row (256 + 8 pad)
#define ZSB 528                 // bytes per smem row
#define ESHB (BN * ZSB)         // 33792 bytes per e buffer

// smem byte offsets
#define OFF_Z    0
#define OFF_E    (BM * ZSB)                    // 67584
#define OFF_EN   (OFF_E + 2 * ESHB)           // 135168
#define OFF_CNT  (OFF_EN + KCODE * 4)         // 137216
#define OFF_CAND (OFF_CNT + BM * 4)           // 137728
#define SMEM_TOTAL (OFF_CAND + BM * CAP * 4)  // 145920

// --------------------------- scratch (device globals) -----------------------
__device__ __nv_bfloat16 g_eb[KCODE * CDIM];
__device__ float         g_enf[KCODE];
__device__ int           g_cnt[NVEC];
__device__ int           g_cand[NVEC * CAP];
__device__ int           g_best[NVEC];
__device__ int           g_queue[NVEC];
__device__ int           g_qcnt;

// --------------------------- asm helpers -------------------------------------
__device__ __forceinline__ uint32_t sptr(const void* p) {
    return (uint32_t)__cvta_generic_to_shared(p);
}
__device__ __forceinline__ void cp16(uint32_t dst, const void* src) {
    asm volatile("cp.async.cg.shared.global [%0], [%1], 16;" :: "r"(dst), "l"(src));
}
__device__ __forceinline__ void ldsm_x4(uint32_t* d, uint32_t addr) {
    asm volatile("ldmatrix.sync.aligned.m8n8.x4.shared.b16 {%0,%1,%2,%3}, [%4];"
                 : "=r"(d[0]), "=r"(d[1]), "=r"(d[2]), "=r"(d[3]) : "r"(addr));
}
__device__ __forceinline__ void mma16816(float* c, const uint32_t* a, const uint32_t* b) {
    asm volatile(
        "mma.sync.aligned.m16n8k16.row.col.f32.bf16.bf16.f32 "
        "{%0,%1,%2,%3}, {%4,%5,%6,%7}, {%8,%9}, {%0,%1,%2,%3};"
        : "+f"(c[0]), "+f"(c[1]), "+f"(c[2]), "+f"(c[3])
        : "r"(a[0]), "r"(a[1]), "r"(a[2]), "r"(a[3]), "r"(b[0]), "r"(b[1]));
}

// --------------------------- 1) codebook prep --------------------------------
__global__ void k_prep_e(const float* __restrict__ e) {
    int k = blockIdx.x, c = threadIdx.x;
    float v = e[k * CDIM + c];
    g_eb[k * CDIM + c] = __float2bfloat16(v);
    float ss = v * v;
    #pragma unroll
    for (int off = 16; off > 0; off >>= 1)
        ss += __shfl_xor_sync(0xFFFFFFFFu, ss, off);
    __shared__ float part[8];
    if ((c & 31) == 0) part[c >> 5] = ss;
    __syncthreads();
    if (c == 0) {
        float t = 0.0f;
        #pragma unroll
        for (int i = 0; i < 8; i++) t += part[i];
        g_enf[k] = t;
    }
}

// --------------------------- 2) queue reset ----------------------------------
__global__ void k_zero() { g_qcnt = 0; }

// --------------------------- 3) GEMM + argmin + candidates + classify --------
__global__ void __launch_bounds__(256, 1)
k_gemm_argmin(const float* __restrict__ x) {
    extern __shared__ char sm[];
    __nv_bfloat16* zsh  = (__nv_bfloat16*)(sm + OFF_Z);
    float*         ensh = (float*)(sm + OFF_EN);
    int*           scnt = (int*)(sm + OFF_CNT);
    int*           scand= (int*)(sm + OFF_CAND);

    const int tid = threadIdx.x;
    const int n0  = blockIdx.x * BM;
    const int bb  = n0 >> 10;
    const int hw0 = n0 & 1023;

    if (tid < BM) scnt[tid] = 0;
    for (int i = tid; i < KCODE; i += 256) ensh[i] = g_enf[i];

    // ---- z tile [128 hw][256 c] transposed+bf16, float4-vectorized ----
    const float* xb = x + (size_t)bb * CDIM * HW + hw0;
    #pragma unroll 4
    for (int it = 0; it < 32; it++) {
        int idx = tid + it * 256;
        int c = idx >> 5, i4 = idx & 31;
        float4 v = *(const float4*)&xb[(size_t)c * HW + i4 * 4];
        zsh[(i4 * 4 + 0) * ZS + c] = __float2bfloat16(v.x);
        zsh[(i4 * 4 + 1) * ZS + c] = __float2bfloat16(v.y);
        zsh[(i4 * 4 + 2) * ZS + c] = __float2bfloat16(v.z);
        zsh[(i4 * 4 + 3) * ZS + c] = __float2bfloat16(v.w);
    }

    const uint32_t zbase = sptr(sm + OFF_Z);
    const uint32_t ebase = sptr(sm + OFF_E);

    // ---- prefetch e chunk 0 ----
    {
        #pragma unroll
        for (int i = 0; i < 8; i++) {
            int idx = tid + i * 256;
            int r = idx >> 5, s = idx & 31;
            cp16(ebase + r * ZSB + s * 16, (const char*)g_eb + (size_t)r * 512 + s * 16);
        }
        asm volatile("cp.async.commit_group;");
    }

    const int lane = tid & 31, wid = tid >> 5;
    const int qr = lane >> 2, qc = lane & 3;
    const int rowbase = wid * 16;

    // ldmatrix lane address offsets (bytes)
    const uint32_t aoff = (uint32_t)(rowbase + (lane & 7) + ((lane >> 3) & 1) * 8) * ZSB
                        + ((lane >> 4) & 1) * 16;
    const uint32_t boff = (uint32_t)((lane & 7) + ((lane >> 4) & 1) * 8) * ZSB
                        + ((lane >> 3) & 1) * 16;

    float rmin0 = 3.0e38f, rmin1 = 3.0e38f;
    const int row0 = rowbase + qr, row1 = rowbase + 8 + qr;

    for (int ck = 0; ck < NCHUNK; ck++) {
        // prefetch next chunk into the other buffer
        if (ck + 1 < NCHUNK) {
            const char* src = (const char*)g_eb + (size_t)(ck + 1) * BN * 512;
            uint32_t dst = ebase + ((ck + 1) & 1) * ESHB;
            #pragma unroll
            for (int i = 0; i < 8; i++) {
                int idx = tid + i * 256;
                int r = idx >> 5, s = idx & 31;
                cp16(dst + r * ZSB + s * 16, src + (size_t)r * 512 + s * 16);
            }
            asm volatile("cp.async.commit_group;");
            asm volatile("cp.async.wait_group 1;");
        } else {
            asm volatile("cp.async.wait_group 0;");
        }
        __syncthreads();   // chunk ck data (and, at ck=0, the z tile) visible

        const uint32_t eb = ebase + (ck & 1) * ESHB;

        float acc[8][4];
        #pragma unroll
        for (int nt = 0; nt < 8; nt++)
            #pragma unroll
            for (int i = 0; i < 4; i++) acc[nt][i] = 0.0f;

        #pragma unroll
        for (int kk = 0; kk < 16; kk++) {
            uint32_t afr[4];
            ldsm_x4(afr, zbase + aoff + kk * 32);
            uint32_t bfr[4][4];
            #pragma unroll
            for (int p = 0; p < 4; p++)
                ldsm_x4(bfr[p], eb + boff + p * (16 * ZSB) + kk * 32);
            #pragma unroll
            for (int p = 0; p < 4; p++) {
                mma16816(acc[2 * p + 0], afr, &bfr[p][0]);
                mma16816(acc[2 * p + 1], afr, &bfr[p][2]);
            }
        }

        // ---- pass 1: scores in place + warp-exact running min ----
        float m0 = 3.0e38f, m1 = 3.0e38f;
        #pragma unroll
        for (int nt = 0; nt < 8; nt++) {
            float en0 = ensh[ck * BN + nt * 8 + 2 * qc + 0];
            float en1 = ensh[ck * BN + nt * 8 + 2 * qc + 1];
            acc[nt][0] = en0 - 2.0f * acc[nt][0];
            acc[nt][1] = en1 - 2.0f * acc[nt][1];
            acc[nt][2] = en0 - 2.0f * acc[nt][2];
            acc[nt][3] = en1 - 2.0f * acc[nt][3];
            m0 = fminf(m0, fminf(acc[nt][0], acc[nt][1]));
            m1 = fminf(m1, fminf(acc[nt][2], acc[nt][3]));
        }
        m0 = fminf(m0, __shfl_xor_sync(0xFFFFFFFFu, m0, 1));
        m0 = fminf(m0, __shfl_xor_sync(0xFFFFFFFFu, m0, 2));
        m1 = fminf(m1, __shfl_xor_sync(0xFFFFFFFFu, m1, 1));
        m1 = fminf(m1, __shfl_xor_sync(0xFFFFFFFFu, m1, 2));
        rmin0 = fminf(rmin0, m0);
        rmin1 = fminf(rmin1, m1);
        const float thr0 = rmin0 + MARGIN, thr1 = rmin1 + MARGIN;

        // ---- pass 2: hit bitmask, rare slow-path push ----
        uint32_t hm0 = 0, hm1 = 0;
        #pragma unroll
        for (int nt = 0; nt < 8; nt++) {
            hm0 |= (acc[nt][0] <= thr0) ? (1u << (2 * nt + 0)) : 0u;
            hm0 |= (acc[nt][1] <= thr0) ? (1u << (2 * nt + 1)) : 0u;
            hm1 |= (acc[nt][2] <= thr1) ? (1u << (2 * nt + 0)) : 0u;
            hm1 |= (acc[nt][3] <= thr1) ? (1u << (2 * nt + 1)) : 0u;
        }
        if (hm0) {
            do {
                int b = __ffs(hm0) - 1; hm0 &= hm0 - 1;
                int kg = ck * BN + (b >> 1) * 8 + 2 * qc + (b & 1);
                int p = atomicAdd(&scnt[row0], 1);
                if (p < CAP) scand[row0 * CAP + p] = kg;
            } while (hm0);
        }
        if (hm1) {
            do {
                int b = __ffs(hm1) - 1; hm1 &= hm1 - 1;
                int kg = ck * BN + (b >> 1) * 8 + 2 * qc + (b & 1);
                int p = atomicAdd(&scnt[row1], 1);
                if (p < CAP) scand[row1 * CAP + p] = kg;
            } while (hm1);
        }
        __syncthreads();   // all reads of buf[ck&1] done before it is refilled
    }

    // ---- write out + inline classify ----
    for (int t = tid; t < BM * CAP; t += 256) g_cand[(size_t)n0 * CAP + t] = scand[t];
    for (int t = tid; t < BM; t += 256) {
        int cnt = scnt[t];
        g_cnt[n0 + t] = cnt;
        if (cnt == 1) {
            g_best[n0 + t] = scand[t * CAP];
        } else {
            int p = atomicAdd(&g_qcnt, 1);
            g_queue[p] = n0 + t;
        }
    }
}

// --------------------------- 4) fp64 exact rescore ---------------------------
__global__ void k_rescore(const float* __restrict__ x, const float* __restrict__ e) {
    const int lane = threadIdx.x & 31;
    const int wglob = (blockIdx.x * blockDim.x + threadIdx.x) >> 5;
    const int nwarps = (gridDim.x * blockDim.x) >> 5;
    const int q = g_qcnt;

    for (int it = wglob; it < q; it += nwarps) {
        int n = g_queue[it];
        int bb = n >> 10, hw = n & 1023;
        const float* xp = x + (size_t)bb * CDIM * HW + hw;
        float z[8];
        #pragma unroll
        for (int j = 0; j < 8; j++) z[j] = xp[(size_t)(lane + 32 * j) * HW];

        int cnt = g_cnt[n];
        double bestS = 1e300;
        int bestK = 0x7FFFFFFF;
        const bool overflow = (cnt > CAP);
        const int iters = overflow ? KCODE : cnt;
        for (int i = 0; i < iters; i++) {
            int k = overflow ? i : g_cand[(size_t)n * CAP + i];
            const float* er = e + (size_t)k * CDIM;
            double d = 0.0, en = 0.0;
            #pragma unroll
            for (int j = 0; j < 8; j++) {
                double ev = (double)er[lane + 32 * j];
                d  += (double)z[j] * ev;
                en += ev * ev;
            }
            #pragma unroll
            for (int off = 16; off > 0; off >>= 1) {
                d  += __shfl_xor_sync(0xFFFFFFFFu, d, off);
                en += __shfl_xor_sync(0xFFFFFFFFu, en, off);
            }
            double s = en - 2.0 * d;
            if (s < bestS || (s == bestS && k < bestK)) { bestS = s; bestK = k; }
        }
        if (lane == 0) g_best[n] = bestK;
    }
}

// --------------------------- 5) gather ---------------------------------------
__global__ void k_gather(const float* __restrict__ e, float* __restrict__ out) {
    __shared__ float rows[32][257];
    __shared__ int sidx[32];
    const int tid = threadIdx.x, lane = tid & 31, wid = tid >> 5;
    const int n0 = blockIdx.x * 32;
    const int bb = n0 >> 10, hw0 = n0 & 1023;

    if (tid < 32) sidx[tid] = g_best[n0 + tid];
    __syncthreads();

    for (int v = wid; v < 32; v += 8) {
        const float* er = e + (size_t)sidx[v] * CDIM;
        #pragma unroll
        for (int j = 0; j < 8; j++) rows[v][lane + 32 * j] = er[lane + 32 * j];
    }
    __syncthreads();

    for (int c = wid; c < CDIM; c += 8)
        out[((size_t)bb * CDIM + c) * HW + hw0 + lane] = rows[lane][c];
}

// --------------------------- launch ------------------------------------------
extern "C" void kernel_launch(void* const* d_in, const int* in_sizes, int n_in,
                              void* d_out, int out_size) {
    const float* x = (const float*)d_in[0];
    const float* e = (const float*)d_in[1];
    if (n_in >= 2 && in_sizes[0] == KCODE * CDIM) {  // robust to input order
        x = (const float*)d_in[1];
        e = (const float*)d_in[0];
    }
    float* out = (float*)d_out;

    cudaFuncSetAttribute(k_gemm_argmin, cudaFuncAttributeMaxDynamicSharedMemorySize,
                         SMEM_TOTAL);

    k_prep_e<<<KCODE, CDIM>>>(e);
    k_zero<<<1, 1>>>();
    k_gemm_argmin<<<NVEC / BM, 256, SMEM_TOTAL>>>(x);
    k_rescore<<<296, 256>>>(x, e);
    k_gather<<<NVEC / 32, 256>>>(e, out);
}

// round 5
// speedup vs baseline: 1.5299x; 1.3512x over previous
#include <cuda_runtime.h>
#include <cuda_bf16.h>
#include <cstdint>

// ============================================================================
// VQ quantizer: for each of N=131072 vectors z (C=256), argmin_k over K=512
// codes of ||z-e_k||^2, output e[argmin] in [B,C,H,W] layout.
//
//   1) prep_e:  e fp32 -> bf16 codebook + fp32 ||e_k||^2
//   2) zero:    reset rescore queue counter
//   3) gemm:    bf16 mma.sync GEMM (s_k = ||e_k||^2 - 2 z.e_k), warp-owns-rows
//               running-min + (score,idx) candidate collection, FINAL filter
//               vs rmin_final+FMARGIN, inline classify, compact z export
//   4) rescore: fp64 exact scores for ambiguous rows (coalesced z reads)
//   5) gather:  out[b,c,h,w] = e[best[n]][c]
// ============================================================================

#define BATCH 128
#define CDIM  256
#define HW    1024
#define NVEC  (BATCH * HW)
#define KCODE 512
#define CAP   16
#define MARGIN  2.0f      // per-chunk collection margin (validated passing)
#define FMARGIN 1.5f      // final filter margin (>= 2*bf16 score error bound)
#define MAXQ  49152       // compact z-export capacity (rows)

#define BM 128
#define BN 64
#define NCHUNK (KCODE / BN)
#define ZS  264                 // bf16 elements per smem row (256 + 8 pad)
#define ZSB 528                 // bytes per smem row
#define ESHB (BN * ZSB)         // 33792 bytes per e buffer

// smem byte offsets
#define OFF_Z     0
#define OFF_E     (BM * ZSB)                     // 67584
#define OFF_EN    (OFF_E + 2 * ESHB)             // 135168
#define OFF_CNT   (OFF_EN + KCODE * 4)           // 137216
#define OFF_RMIN  (OFF_CNT + BM * 4)             // 137728
#define OFF_QSLOT (OFF_RMIN + BM * 4)            // 138240
#define OFF_CS    (OFF_QSLOT + BM * 4)           // 138752  candidate scores
#define OFF_CI    (OFF_CS + BM * CAP * 4)        // 146944  candidate indices
#define SMEM_TOTAL (OFF_CI + BM * CAP * 4)       // 155136

// --------------------------- scratch (device globals) -----------------------
__device__ __nv_bfloat16 g_eb[KCODE * CDIM];
__device__ float         g_enf[KCODE];
__device__ int           g_best[NVEC];
__device__ int           g_qn[NVEC];            // queued vector id
__device__ int           g_qc[NVEC];            // survivor count (KCODE = full scan)
__device__ int           g_qcand[NVEC];         // not used; kept small -- see g_qcd
__device__ int           g_qcd[(size_t)NVEC * CAP]; // survivor candidate indices
__device__ float         g_zq[(size_t)MAXQ * CDIM]; // compact fp32 z rows
__device__ int           g_qcnt;

// --------------------------- asm helpers -------------------------------------
__device__ __forceinline__ uint32_t sptr(const void* p) {
    return (uint32_t)__cvta_generic_to_shared(p);
}
__device__ __forceinline__ void cp16(uint32_t dst, const void* src) {
    asm volatile("cp.async.cg.shared.global [%0], [%1], 16;" :: "r"(dst), "l"(src));
}
__device__ __forceinline__ void ldsm_x4(uint32_t* d, uint32_t addr) {
    asm volatile("ldmatrix.sync.aligned.m8n8.x4.shared.b16 {%0,%1,%2,%3}, [%4];"
                 : "=r"(d[0]), "=r"(d[1]), "=r"(d[2]), "=r"(d[3]) : "r"(addr));
}
__device__ __forceinline__ void mma16816(float* c, const uint32_t* a, const uint32_t* b) {
    asm volatile(
        "mma.sync.aligned.m16n8k16.row.col.f32.bf16.bf16.f32 "
        "{%0,%1,%2,%3}, {%4,%5,%6,%7}, {%8,%9}, {%0,%1,%2,%3};"
        : "+f"(c[0]), "+f"(c[1]), "+f"(c[2]), "+f"(c[3])
        : "r"(a[0]), "r"(a[1]), "r"(a[2]), "r"(a[3]), "r"(b[0]), "r"(b[1]));
}

// --------------------------- 1) codebook prep --------------------------------
__global__ void k_prep_e(const float* __restrict__ e) {
    int k = blockIdx.x, c = threadIdx.x;
    float v = e[k * CDIM + c];
    g_eb[k * CDIM + c] = __float2bfloat16(v);
    float ss = v * v;
    #pragma unroll
    for (int off = 16; off > 0; off >>= 1)
        ss += __shfl_xor_sync(0xFFFFFFFFu, ss, off);
    __shared__ float part[8];
    if ((c & 31) == 0) part[c >> 5] = ss;
    __syncthreads();
    if (c == 0) {
        float t = 0.0f;
        #pragma unroll
        for (int i = 0; i < 8; i++) t += part[i];
        g_enf[k] = t;
    }
}

// --------------------------- 2) queue reset ----------------------------------
__global__ void k_zero() { g_qcnt = 0; }

// --------------------------- 3) GEMM + argmin + final filter -----------------
__global__ void __launch_bounds__(256, 1)
k_gemm_argmin(const float* __restrict__ x) {
    extern __shared__ char sm[];
    __nv_bfloat16* zsh   = (__nv_bfloat16*)(sm + OFF_Z);
    float*         ensh  = (float*)(sm + OFF_EN);
    int*           scnt  = (int*)(sm + OFF_CNT);
    float*         rminsh= (float*)(sm + OFF_RMIN);
    int*           qslot = (int*)(sm + OFF_QSLOT);
    float*         cs    = (float*)(sm + OFF_CS);
    int*           ci    = (int*)(sm + OFF_CI);

    const int tid = threadIdx.x;
    const int n0  = blockIdx.x * BM;
    const int bb  = n0 >> 10;
    const int hw0 = n0 & 1023;

    if (tid < BM) scnt[tid] = 0;
    for (int i = tid; i < KCODE; i += 256) ensh[i] = g_enf[i];

    // ---- z tile: coalesced scalar loads, paired bf16x2 stores (4-way max) ----
    const float* xb = x + (size_t)bb * CDIM * HW + hw0;
    #pragma unroll 4
    for (int it = 0; it < 64; it++) {
        int p = tid + it * 256;          // pair index over [128 rows][128 cpairs]
        int cp = p >> 7, i = p & 127;    // lanes vary i -> coalesced loads
        float v0 = xb[(size_t)(2 * cp) * HW + i];
        float v1 = xb[(size_t)(2 * cp + 1) * HW + i];
        __nv_bfloat162 pk = __floats2bfloat162_rn(v0, v1);
        *(__nv_bfloat162*)&zsh[i * ZS + 2 * cp] = pk;
    }

    const uint32_t zbase = sptr(sm + OFF_Z);
    const uint32_t ebase = sptr(sm + OFF_E);

    // ---- prefetch e chunk 0 ----
    {
        #pragma unroll
        for (int i = 0; i < 8; i++) {
            int idx = tid + i * 256;
            int r = idx >> 5, s = idx & 31;
            cp16(ebase + r * ZSB + s * 16, (const char*)g_eb + (size_t)r * 512 + s * 16);
        }
        asm volatile("cp.async.commit_group;");
    }

    const int lane = tid & 31, wid = tid >> 5;
    const int qr = lane >> 2, qc = lane & 3;
    const int rowbase = wid * 16;

    const uint32_t aoff = (uint32_t)(rowbase + (lane & 7) + ((lane >> 3) & 1) * 8) * ZSB
                        + ((lane >> 4) & 1) * 16;
    const uint32_t boff = (uint32_t)((lane & 7) + ((lane >> 4) & 1) * 8) * ZSB
                        + ((lane >> 3) & 1) * 16;

    float rmin0 = 3.0e38f, rmin1 = 3.0e38f;
    const int row0 = rowbase + qr, row1 = rowbase + 8 + qr;

    for (int ck = 0; ck < NCHUNK; ck++) {
        if (ck + 1 < NCHUNK) {
            const char* src = (const char*)g_eb + (size_t)(ck + 1) * BN * 512;
            uint32_t dst = ebase + ((ck + 1) & 1) * ESHB;
            #pragma unroll
            for (int i = 0; i < 8; i++) {
                int idx = tid + i * 256;
                int r = idx >> 5, s = idx & 31;
                cp16(dst + r * ZSB + s * 16, src + (size_t)r * 512 + s * 16);
            }
            asm volatile("cp.async.commit_group;");
            asm volatile("cp.async.wait_group 1;");
        } else {
            asm volatile("cp.async.wait_group 0;");
        }
        __syncthreads();

        const uint32_t eb = ebase + (ck & 1) * ESHB;

        float acc[8][4];
        #pragma unroll
        for (int nt = 0; nt < 8; nt++)
            #pragma unroll
            for (int i = 0; i < 4; i++) acc[nt][i] = 0.0f;

        #pragma unroll
        for (int kk = 0; kk < 16; kk++) {
            uint32_t afr[4];
            ldsm_x4(afr, zbase + aoff + kk * 32);
            uint32_t bfr[4][4];
            #pragma unroll
            for (int p = 0; p < 4; p++)
                ldsm_x4(bfr[p], eb + boff + p * (16 * ZSB) + kk * 32);
            #pragma unroll
            for (int p = 0; p < 4; p++) {
                mma16816(acc[2 * p + 0], afr, &bfr[p][0]);
                mma16816(acc[2 * p + 1], afr, &bfr[p][2]);
            }
        }

        // ---- pass 1: scores in place + exact running min ----
        float m0 = 3.0e38f, m1 = 3.0e38f;
        #pragma unroll
        for (int nt = 0; nt < 8; nt++) {
            float en0 = ensh[ck * BN + nt * 8 + 2 * qc + 0];
            float en1 = ensh[ck * BN + nt * 8 + 2 * qc + 1];
            acc[nt][0] = en0 - 2.0f * acc[nt][0];
            acc[nt][1] = en1 - 2.0f * acc[nt][1];
            acc[nt][2] = en0 - 2.0f * acc[nt][2];
            acc[nt][3] = en1 - 2.0f * acc[nt][3];
            m0 = fminf(m0, fminf(acc[nt][0], acc[nt][1]));
            m1 = fminf(m1, fminf(acc[nt][2], acc[nt][3]));
        }
        m0 = fminf(m0, __shfl_xor_sync(0xFFFFFFFFu, m0, 1));
        m0 = fminf(m0, __shfl_xor_sync(0xFFFFFFFFu, m0, 2));
        m1 = fminf(m1, __shfl_xor_sync(0xFFFFFFFFu, m1, 1));
        m1 = fminf(m1, __shfl_xor_sync(0xFFFFFFFFu, m1, 2));
        rmin0 = fminf(rmin0, m0);
        rmin1 = fminf(rmin1, m1);
        const float thr0 = rmin0 + MARGIN, thr1 = rmin1 + MARGIN;

        // ---- pass 2: rare pushes of (score, idx) ----
        #pragma unroll
        for (int nt = 0; nt < 8; nt++) {
            int kg = ck * BN + nt * 8 + 2 * qc;
            if (acc[nt][0] <= thr0) {
                int p = atomicAdd(&scnt[row0], 1);
                if (p < CAP) { cs[row0 * CAP + p] = acc[nt][0]; ci[row0 * CAP + p] = kg; }
            }
            if (acc[nt][1] <= thr0) {
                int p = atomicAdd(&scnt[row0], 1);
                if (p < CAP) { cs[row0 * CAP + p] = acc[nt][1]; ci[row0 * CAP + p] = kg + 1; }
            }
            if (acc[nt][2] <= thr1) {
                int p = atomicAdd(&scnt[row1], 1);
                if (p < CAP) { cs[row1 * CAP + p] = acc[nt][2]; ci[row1 * CAP + p] = kg; }
            }
            if (acc[nt][3] <= thr1) {
                int p = atomicAdd(&scnt[row1], 1);
                if (p < CAP) { cs[row1 * CAP + p] = acc[nt][3]; ci[row1 * CAP + p] = kg + 1; }
            }
        }
        __syncthreads();
    }

    // ---- publish per-row final mins ----
    if (qc == 0) { rminsh[row0] = rmin0; rminsh[row1] = rmin1; }
    __syncthreads();

    // ---- final filter + classify (128 threads, one row each) ----
    if (tid < BM) {
        int t = tid;
        int cnt = scnt[t];
        int n = n0 + t;
        if (cnt > CAP) {                         // overflow: full-scan fallback
            int q = atomicAdd(&g_qcnt, 1);
            qslot[t] = q; g_qn[q] = n; g_qc[q] = KCODE;
        } else {
            float thr = rminsh[t] + FMARGIN;
            int surv = 0, uniq = 0;
            for (int i = 0; i < cnt; i++)
                if (cs[t * CAP + i] <= thr) { surv++; uniq = ci[t * CAP + i]; }
            if (surv == 1) {
                g_best[n] = uniq; qslot[t] = -1;
            } else {
                int q = atomicAdd(&g_qcnt, 1);
                qslot[t] = q; g_qn[q] = n; g_qc[q] = surv;
                int w = 0;
                for (int i = 0; i < cnt; i++)
                    if (cs[t * CAP + i] <= thr) g_qcd[(size_t)q * CAP + (w++)] = ci[t * CAP + i];
            }
        }
    }
    __syncthreads();

    // ---- compact fp32 z export for queued rows (coalesced rescore reads) ----
    for (int r = 0; r < BM; r++) {
        int q = qslot[r];
        if (q >= 0 && q < MAXQ)
            g_zq[(size_t)q * CDIM + tid] = xb[(size_t)tid * HW + r];
    }
}

// --------------------------- 4) fp64 exact rescore ---------------------------
__global__ void k_rescore(const float* __restrict__ x, const float* __restrict__ e) {
    const int lane = threadIdx.x & 31;
    const int wglob = (blockIdx.x * blockDim.x + threadIdx.x) >> 5;
    const int nwarps = (gridDim.x * blockDim.x) >> 5;
    const int q = g_qcnt;

    for (int it = wglob; it < q; it += nwarps) {
        int n = g_qn[it];
        float z[8];
        if (it < MAXQ) {
            #pragma unroll
            for (int j = 0; j < 8; j++) z[j] = g_zq[(size_t)it * CDIM + lane + 32 * j];
        } else {   // export overflow: strided read from x
            int bb = n >> 10, hw = n & 1023;
            const float* xp = x + (size_t)bb * CDIM * HW + hw;
            #pragma unroll
            for (int j = 0; j < 8; j++) z[j] = xp[(size_t)(lane + 32 * j) * HW];
        }

        int cnt = g_qc[it];
        double bestS = 1e300;
        int bestK = 0x7FFFFFFF;
        const bool full = (cnt >= KCODE);
        const int iters = full ? KCODE : cnt;
        for (int i = 0; i < iters; i++) {
            int k = full ? i : g_qcd[(size_t)it * CAP + i];
            const float* er = e + (size_t)k * CDIM;
            double d = 0.0, en = 0.0;
            #pragma unroll
            for (int j = 0; j < 8; j++) {
                double ev = (double)er[lane + 32 * j];
                d  += (double)z[j] * ev;
                en += ev * ev;
            }
            #pragma unroll
            for (int off = 16; off > 0; off >>= 1) {
                d  += __shfl_xor_sync(0xFFFFFFFFu, d, off);
                en += __shfl_xor_sync(0xFFFFFFFFu, en, off);
            }
            double s = en - 2.0 * d;
            if (s < bestS || (s == bestS && k < bestK)) { bestS = s; bestK = k; }
        }
        if (lane == 0) g_best[n] = bestK;
    }
}

// --------------------------- 5) gather ---------------------------------------
__global__ void k_gather(const float* __restrict__ e, float* __restrict__ out) {
    __shared__ float rows[32][257];
    __shared__ int sidx[32];
    const int tid = threadIdx.x, lane = tid & 31, wid = tid >> 5;
    const int n0 = blockIdx.x * 32;
    const int bb = n0 >> 10, hw0 = n0 & 1023;

    if (tid < 32) sidx[tid] = g_best[n0 + tid];
    __syncthreads();

    for (int v = wid; v < 32; v += 8) {
        const float* er = e + (size_t)sidx[v] * CDIM;
        #pragma unroll
        for (int j = 0; j < 8; j++) rows[v][lane + 32 * j] = er[lane + 32 * j];
    }
    __syncthreads();

    for (int c = wid; c < CDIM; c += 8)
        out[((size_t)bb * CDIM + c) * HW + hw0 + lane] = rows[lane][c];
}

// --------------------------- launch ------------------------------------------
extern "C" void kernel_launch(void* const* d_in, const int* in_sizes, int n_in,
                              void* d_out, int out_size) {
    const float* x = (const float*)d_in[0];
    const float* e = (const float*)d_in[1];
    if (n_in >= 2 && in_sizes[0] == KCODE * CDIM) {  // robust to input order
        x = (const float*)d_in[1];
        e = (const float*)d_in[0];
    }
    float* out = (float*)d_out;

    cudaFuncSetAttribute(k_gemm_argmin, cudaFuncAttributeMaxDynamicSharedMemorySize,
                         SMEM_TOTAL);

    k_prep_e<<<KCODE, CDIM>>>(e);
    k_zero<<<1, 1>>>();
    k_gemm_argmin<<<NVEC / BM, 256, SMEM_TOTAL>>>(x);
    k_rescore<<<296, 256>>>(x, e);
    k_gather<<<NVEC / 32, 256>>>(e, out);
}

// round 8
// speedup vs baseline: 1.9180x; 1.2537x over previous
#include <cuda_runtime.h>
#include <cuda_bf16.h>
#include <cstdint>

// ============================================================================
// VQ quantizer: for each of N=131072 vectors z (C=256), argmin_k over K=512
// codes of ||z-e_k||^2, output e[argmin] in [B,C,H,W] layout.
//
//   1) prep_e:  e fp32 -> bf16 codebook + fp32 ||e_k||^2
//   2) zero:    reset rescore queue counter
//   3) gemm:    bf16 mma.sync GEMM (s_k = ||e_k||^2 - 2 z.e_k), warp-owns-rows
//               running-min + (score,idx) candidate collection (global slots),
//               final filter vs rmin_final+FMARGIN, inline classify, z export.
//               2 CTAs/SM (102.5KB smem), single-buffer B w/ epilogue overlap.
//   4) rescore: fp64 exact scores for ambiguous rows (coalesced z reads)
//   5) gather:  out[b,c,h,w] = e[best[n]][c]
// ============================================================================

#define BATCH 128
#define CDIM  256
#define HW    1024
#define NVEC  (BATCH * HW)
#define KCODE 512
#define CAP   16
#define MARGIN  2.0f      // per-chunk collection margin (validated)
#define FMARGIN 1.5f      // final filter margin (validated)
#define MAXQ  49152

#define BM 128
#define BN 64
#define NCHUNK (KCODE / BN)
#define ZS  264                 // bf16 elements per smem row (256 + 8 pad)
#define ZSB 528                 // bytes per smem row (132 mod 32 banks = 4: ldsm-clean)

// smem byte offsets (102.5 KB total -> 2 CTAs/SM)
#define OFF_EN    0                        // 512 f32   -> 2048
#define OFF_CNT   2048                     // 128 i32   -> 2560
#define OFF_RMIN  2560                     // 128 f32   -> 3072
#define OFF_QSLOT 3072                     // 128 i32   -> 3584
#define OFF_Z     3584                     // 128*528   -> 71168
#define OFF_E     71168                    // 64*528    -> 104960
#define SMEM_TOTAL 104960

// --------------------------- scratch (device globals) -----------------------
__device__ __nv_bfloat16 g_eb[KCODE * CDIM];
__device__ float         g_enf[KCODE];
__device__ int           g_best[NVEC];
__device__ float         g_csv[(size_t)NVEC * CAP];   // candidate scores
__device__ int           g_civ[(size_t)NVEC * CAP];   // candidate indices
__device__ int           g_qn[NVEC];
__device__ int           g_qc[NVEC];
__device__ int           g_qcd[(size_t)NVEC * CAP];
__device__ float         g_zq[(size_t)MAXQ * CDIM];
__device__ int           g_qcnt;

// --------------------------- asm helpers -------------------------------------
__device__ __forceinline__ uint32_t sptr(const void* p) {
    return (uint32_t)__cvta_generic_to_shared(p);
}
__device__ __forceinline__ void cp16(uint32_t dst, const void* src) {
    asm volatile("cp.async.cg.shared.global [%0], [%1], 16;" :: "r"(dst), "l"(src));
}
__device__ __forceinline__ void ldsm_x4(uint32_t* d, uint32_t addr) {
    asm volatile("ldmatrix.sync.aligned.m8n8.x4.shared.b16 {%0,%1,%2,%3}, [%4];"
                 : "=r"(d[0]), "=r"(d[1]), "=r"(d[2]), "=r"(d[3]) : "r"(addr));
}
__device__ __forceinline__ void mma16816(float* c, const uint32_t* a, const uint32_t* b) {
    asm volatile(
        "mma.sync.aligned.m16n8k16.row.col.f32.bf16.bf16.f32 "
        "{%0,%1,%2,%3}, {%4,%5,%6,%7}, {%8,%9}, {%0,%1,%2,%3};"
        : "+f"(c[0]), "+f"(c[1]), "+f"(c[2]), "+f"(c[3])
        : "r"(a[0]), "r"(a[1]), "r"(a[2]), "r"(a[3]), "r"(b[0]), "r"(b[1]));
}

// --------------------------- 1) codebook prep --------------------------------
__global__ void k_prep_e(const float* __restrict__ e) {
    int k = blockIdx.x, c = threadIdx.x;
    float v = e[k * CDIM + c];
    g_eb[k * CDIM + c] = __float2bfloat16(v);
    float ss = v * v;
    #pragma unroll
    for (int off = 16; off > 0; off >>= 1)
        ss += __shfl_xor_sync(0xFFFFFFFFu, ss, off);
    __shared__ float part[8];
    if ((c & 31) == 0) part[c >> 5] = ss;
    __syncthreads();
    if (c == 0) {
        float t = 0.0f;
        #pragma unroll
        for (int i = 0; i < 8; i++) t += part[i];
        g_enf[k] = t;
    }
}

// --------------------------- 2) queue reset ----------------------------------
__global__ void k_zero() { g_qcnt = 0; }

// --------------------------- 3) GEMM + argmin + final filter -----------------
__global__ void __launch_bounds__(256, 2)
k_gemm_argmin(const float* __restrict__ x) {
    extern __shared__ char sm[];
    float* ensh  = (float*)(sm + OFF_EN);
    int*   scnt  = (int*)(sm + OFF_CNT);
    float* rminsh= (float*)(sm + OFF_RMIN);
    int*   qslot = (int*)(sm + OFF_QSLOT);
    __nv_bfloat16* zsh = (__nv_bfloat16*)(sm + OFF_Z);

    const int tid = threadIdx.x;
    const int n0  = blockIdx.x * BM;
    const int bb  = n0 >> 10;
    const int hw0 = n0 & 1023;

    if (tid < BM) scnt[tid] = 0;
    for (int i = tid; i < KCODE; i += 256) ensh[i] = g_enf[i];

    const uint32_t zbase = sptr(sm + OFF_Z);
    const uint32_t ebase = sptr(sm + OFF_E);

    // ---- B chunk loader: single buffer, one commit group per chunk ----
    auto loadB = [&](int ck) {
        const char* src = (const char*)g_eb + (size_t)ck * BN * 512;
        #pragma unroll
        for (int i = 0; i < 8; i++) {
            int t = tid + i * 256;
            int r = t >> 5, s = t & 31;
            cp16(ebase + r * ZSB + s * 16, src + (size_t)r * 512 + s * 16);
        }
        asm volatile("cp.async.commit_group;");
    };
    loadB(0);   // prefetch chunk 0 behind the z-tile transpose

    // ---- z tile: coalesced loads, paired bf16x2 stores ----
    const float* xb = x + (size_t)bb * CDIM * HW + hw0;
    #pragma unroll 4
    for (int it = 0; it < 64; it++) {
        int p = tid + it * 256;
        int cp = p >> 7, i = p & 127;
        float v0 = xb[(size_t)(2 * cp) * HW + i];
        float v1 = xb[(size_t)(2 * cp + 1) * HW + i];
        *(__nv_bfloat162*)&zsh[i * ZS + 2 * cp] = __floats2bfloat162_rn(v0, v1);
    }

    const int lane = tid & 31, wid = tid >> 5;
    const int qr = lane >> 2, qc = lane & 3;
    const int rowbase = wid * 16;

    const uint32_t aoff = (uint32_t)(rowbase + (lane & 7) + ((lane >> 3) & 1) * 8) * ZSB
                        + ((lane >> 4) & 1) * 16;
    const uint32_t boff = (uint32_t)((lane & 7) + ((lane >> 4) & 1) * 8) * ZSB
                        + ((lane >> 3) & 1) * 16;

    float rmin0 = 3.0e38f, rmin1 = 3.0e38f;
    const int row0 = rowbase + qr, row1 = rowbase + 8 + qr;

    for (int ck = 0; ck < NCHUNK; ck++) {
        asm volatile("cp.async.wait_group 0;");
        __syncthreads();                 // B(ck) visible (z tile too at ck=0)

        float acc[8][4];
        #pragma unroll
        for (int nt = 0; nt < 8; nt++)
            #pragma unroll
            for (int i = 0; i < 4; i++) acc[nt][i] = 0.0f;

        #pragma unroll
        for (int kk = 0; kk < 16; kk++) {
            uint32_t afr[4];
            ldsm_x4(afr, zbase + aoff + kk * 32);
            uint32_t bfr[4][4];
            #pragma unroll
            for (int p = 0; p < 4; p++)
                ldsm_x4(bfr[p], ebase + boff + p * (16 * ZSB) + kk * 32);
            #pragma unroll
            for (int p = 0; p < 4; p++) {
                mma16816(acc[2 * p + 0], afr, &bfr[p][0]);
                mma16816(acc[2 * p + 1], afr, &bfr[p][2]);
            }
        }
        __syncthreads();                 // all warps done reading B(ck)
        if (ck + 1 < NCHUNK) loadB(ck + 1);   // overlaps with epilogue below

        // ---- pass 1: scores in place + exact running min ----
        float m0 = 3.0e38f, m1 = 3.0e38f;
        #pragma unroll
        for (int nt = 0; nt < 8; nt++) {
            float en0 = ensh[ck * BN + nt * 8 + 2 * qc + 0];
            float en1 = ensh[ck * BN + nt * 8 + 2 * qc + 1];
            acc[nt][0] = en0 - 2.0f * acc[nt][0];
            acc[nt][1] = en1 - 2.0f * acc[nt][1];
            acc[nt][2] = en0 - 2.0f * acc[nt][2];
            acc[nt][3] = en1 - 2.0f * acc[nt][3];
            m0 = fminf(m0, fminf(acc[nt][0], acc[nt][1]));
            m1 = fminf(m1, fminf(acc[nt][2], acc[nt][3]));
        }
        m0 = fminf(m0, __shfl_xor_sync(0xFFFFFFFFu, m0, 1));
        m0 = fminf(m0, __shfl_xor_sync(0xFFFFFFFFu, m0, 2));
        m1 = fminf(m1, __shfl_xor_sync(0xFFFFFFFFu, m1, 1));
        m1 = fminf(m1, __shfl_xor_sync(0xFFFFFFFFu, m1, 2));
        rmin0 = fminf(rmin0, m0);
        rmin1 = fminf(rmin1, m1);
        const float thr0 = rmin0 + MARGIN, thr1 = rmin1 + MARGIN;

        // ---- pass 2: rare pushes of (score, idx) to global slots ----
        #pragma unroll
        for (int nt = 0; nt < 8; nt++) {
            int kg = ck * BN + nt * 8 + 2 * qc;
            if (acc[nt][0] <= thr0) {
                int p = atomicAdd(&scnt[row0], 1);
                if (p < CAP) { g_csv[(size_t)(n0 + row0) * CAP + p] = acc[nt][0];
                               g_civ[(size_t)(n0 + row0) * CAP + p] = kg; }
            }
            if (acc[nt][1] <= thr0) {
                int p = atomicAdd(&scnt[row0], 1);
                if (p < CAP) { g_csv[(size_t)(n0 + row0) * CAP + p] = acc[nt][1];
                               g_civ[(size_t)(n0 + row0) * CAP + p] = kg + 1; }
            }
            if (acc[nt][2] <= thr1) {
                int p = atomicAdd(&scnt[row1], 1);
                if (p < CAP) { g_csv[(size_t)(n0 + row1) * CAP + p] = acc[nt][2];
                               g_civ[(size_t)(n0 + row1) * CAP + p] = kg; }
            }
            if (acc[nt][3] <= thr1) {
                int p = atomicAdd(&scnt[row1], 1);
                if (p < CAP) { g_csv[(size_t)(n0 + row1) * CAP + p] = acc[nt][3];
                               g_civ[(size_t)(n0 + row1) * CAP + p] = kg + 1; }
            }
        }
    }

    // ---- publish per-row final mins ----
    if (qc == 0) { rminsh[row0] = rmin0; rminsh[row1] = rmin1; }
    __syncthreads();

    // ---- final filter + classify (128 threads, one row each) ----
    if (tid < BM) {
        int t = tid, n = n0 + t;
        int cnt = scnt[t];
        if (cnt > CAP) {                         // overflow: full-scan fallback
            int q = atomicAdd(&g_qcnt, 1);
            qslot[t] = q; g_qn[q] = n; g_qc[q] = KCODE;
        } else {
            float thr = rminsh[t] + FMARGIN;
            int surv = 0, uniq = 0;
            for (int i = 0; i < cnt; i++)
                if (g_csv[(size_t)n * CAP + i] <= thr) { surv++; uniq = g_civ[(size_t)n * CAP + i]; }
            if (surv == 1) {
                g_best[n] = uniq; qslot[t] = -1;
            } else {
                int q = atomicAdd(&g_qcnt, 1);
                qslot[t] = q; g_qn[q] = n; g_qc[q] = surv;
                int w = 0;
                for (int i = 0; i < cnt; i++)
                    if (g_csv[(size_t)n * CAP + i] <= thr)
                        g_qcd[(size_t)q * CAP + (w++)] = g_civ[(size_t)n * CAP + i];
            }
        }
    }
    __syncthreads();

    // ---- compact fp32 z export for queued rows (coalesced rescore reads) ----
    for (int r = 0; r < BM; r++) {
        int q = qslot[r];
        if (q >= 0 && q < MAXQ)
            g_zq[(size_t)q * CDIM + tid] = xb[(size_t)tid * HW + r];
    }
}

// --------------------------- 4) fp64 exact rescore ---------------------------
__global__ void k_rescore(const float* __restrict__ x, const float* __restrict__ e) {
    const int lane = threadIdx.x & 31;
    const int wglob = (blockIdx.x * blockDim.x + threadIdx.x) >> 5;
    const int nwarps = (gridDim.x * blockDim.x) >> 5;
    const int q = g_qcnt;

    for (int it = wglob; it < q; it += nwarps) {
        int n = g_qn[it];
        float z[8];
        if (it < MAXQ) {
            #pragma unroll
            for (int j = 0; j < 8; j++) z[j] = g_zq[(size_t)it * CDIM + lane + 32 * j];
        } else {   // export overflow: strided read from x
            int bb = n >> 10, hw = n & 1023;
            const float* xp = x + (size_t)bb * CDIM * HW + hw;
            #pragma unroll
            for (int j = 0; j < 8; j++) z[j] = xp[(size_t)(lane + 32 * j) * HW];
        }

        int cnt = g_qc[it];
        double bestS = 1e300;
        int bestK = 0x7FFFFFFF;
        const bool full = (cnt >= KCODE);
        const int iters = full ? KCODE : cnt;
        for (int i = 0; i < iters; i++) {
            int k = full ? i : g_qcd[(size_t)it * CAP + i];
            const float* er = e + (size_t)k * CDIM;
            double d = 0.0, en = 0.0;
            #pragma unroll
            for (int j = 0; j < 8; j++) {
                double ev = (double)er[lane + 32 * j];
                d  += (double)z[j] * ev;
                en += ev * ev;
            }
            #pragma unroll
            for (int off = 16; off > 0; off >>= 1) {
                d  += __shfl_xor_sync(0xFFFFFFFFu, d, off);
                en += __shfl_xor_sync(0xFFFFFFFFu, en, off);
            }
            double s = en - 2.0 * d;
            if (s < bestS || (s == bestS && k < bestK)) { bestS = s; bestK = k; }
        }
        if (lane == 0) g_best[n] = bestK;
    }
}

// --------------------------- 5) gather ---------------------------------------
__global__ void k_gather(const float* __restrict__ e, float* __restrict__ out) {
    __shared__ float rows[32][257];
    __shared__ int sidx[32];
    const int tid = threadIdx.x, lane = tid & 31, wid = tid >> 5;
    const int n0 = blockIdx.x * 32;
    const int bb = n0 >> 10, hw0 = n0 & 1023;

    if (tid < 32) sidx[tid] = g_best[n0 + tid];
    __syncthreads();

    for (int v = wid; v < 32; v += 8) {
        const float* er = e + (size_t)sidx[v] * CDIM;
        #pragma unroll
        for (int j = 0; j < 8; j++) rows[v][lane + 32 * j] = er[lane + 32 * j];
    }
    __syncthreads();

    for (int c = wid; c < CDIM; c += 8)
        out[((size_t)bb * CDIM + c) * HW + hw0 + lane] = rows[lane][c];
}

// --------------------------- launch ------------------------------------------
extern "C" void kernel_launch(void* const* d_in, const int* in_sizes, int n_in,
                              void* d_out, int out_size) {
    const float* x = (const float*)d_in[0];
    const float* e = (const float*)d_in[1];
    if (n_in >= 2 && in_sizes[0] == KCODE * CDIM) {  // robust to input order
        x = (const float*)d_in[1];
        e = (const float*)d_in[0];
    }
    float* out = (float*)d_out;

    cudaFuncSetAttribute(k_gemm_argmin, cudaFuncAttributeMaxDynamicSharedMemorySize,
                         SMEM_TOTAL);

    k_prep_e<<<KCODE, CDIM>>>(e);
    k_zero<<<1, 1>>>();
    k_gemm_argmin<<<NVEC / BM, 256, SMEM_TOTAL>>>(x);
    k_rescore<<<296, 256>>>(x, e);
    k_gather<<<NVEC / 32, 256>>>(e, out);
}